// round 8
// baseline (speedup 1.0000x reference)
#include <cuda_runtime.h>

#define N_NODES 50000
#define N_EDGES 800000
#define CH 128
#define SCAN_CHUNK 512
#define SCAN_BLOCKS ((N_NODES + SCAN_CHUNK - 1) / SCAN_CHUNK)   // 98

// ---------------- scratch (static device globals; no runtime alloc) ----------------
__device__ float g_featA[N_NODES * CH];
__device__ float g_featB[N_NODES * CH];
__device__ float g_agg[N_NODES * CH];
__device__ int   g_deg[N_NODES];
__device__ int   g_start[N_NODES];
__device__ int   g_cursor[N_NODES];
__device__ int   g_src[N_EDGES];
__device__ int   g_part[SCAN_BLOCKS];
__device__ int   g_is64;

// ---------------- init: block 0 detects edge-index layout, others zero g_deg ----------
// int64 layout: hi int32 word of the first 4096 edges is always 0 (ids < 50000).
__global__ void init_kernel(const int* __restrict__ ei32) {
    if (blockIdx.x == 0) {
        __shared__ int any_nz;
        if (threadIdx.x == 0) any_nz = 0;
        __syncthreads();
        for (int i = threadIdx.x; i < 4096; i += blockDim.x)
            if (ei32[2 * i + 1] != 0) any_nz = 1;    // benign race
        __syncthreads();
        if (threadIdx.x == 0) g_is64 = any_nz ? 0 : 1;
    } else {
        int i = (blockIdx.x - 1) * blockDim.x + threadIdx.x;
        if (i < N_NODES) g_deg[i] = 0;
    }
}

__device__ __forceinline__ int load_idx(const int* ei32, long long pos) {
    int v = g_is64 ? ei32[2 * pos] : ei32[pos];
    if (v < 0 || v >= N_NODES) v = 0;                // crash-proof clamp
    return v;
}

__global__ void hist_kernel(const int* __restrict__ ei32) {
    int e = blockIdx.x * blockDim.x + threadIdx.x;
    if (e < N_EDGES) atomicAdd(&g_deg[load_idx(ei32, (long long)N_EDGES + e)], 1);
}

// ---------------- parallel 3-phase exclusive scan of g_deg -> g_start/g_cursor -------
__global__ void scan_local_kernel() {   // 98 blocks x 512: local excl scan + block total
    __shared__ int warp_sums[16];
    int tid = threadIdx.x, lane = tid & 31, wid = tid >> 5;
    int i = blockIdx.x * SCAN_CHUNK + tid;
    int v = (i < N_NODES) ? g_deg[i] : 0;
    int val = v;
    #pragma unroll
    for (int off = 1; off < 32; off <<= 1) {
        int t = __shfl_up_sync(0xffffffffu, val, off);
        if (lane >= off) val += t;
    }
    if (lane == 31) warp_sums[wid] = val;
    __syncthreads();
    if (wid == 0 && lane < 16) {
        int s = warp_sums[lane], sv = s;
        #pragma unroll
        for (int off = 1; off < 16; off <<= 1) {
            int t = __shfl_up_sync(0x0000ffffu, sv, off);
            if (lane >= off) sv += t;
        }
        warp_sums[lane] = sv - s;       // exclusive warp offsets
    }
    __syncthreads();
    int excl = val - v + warp_sums[wid];
    if (i < N_NODES) g_start[i] = excl;
    if (tid == SCAN_CHUNK - 1) g_part[blockIdx.x] = excl + v;
}

__global__ void scan_part_kernel() {    // 1 block x 128: excl scan of 98 partials
    __shared__ int sh[128];
    int tid = threadIdx.x;
    int v = (tid < SCAN_BLOCKS) ? g_part[tid] : 0;
    sh[tid] = v;
    __syncthreads();
    for (int off = 1; off < 128; off <<= 1) {
        int t = (tid >= off) ? sh[tid - off] : 0;
        __syncthreads();
        sh[tid] += t;
        __syncthreads();
    }
    if (tid < SCAN_BLOCKS) g_part[tid] = sh[tid] - v;
}

__global__ void scan_add_kernel() {     // 98 blocks x 512: add block offset
    int i = blockIdx.x * SCAN_CHUNK + threadIdx.x;
    if (i < N_NODES) {
        int val = g_start[i] + g_part[blockIdx.x];
        g_start[i]  = val;
        g_cursor[i] = val;
    }
}

__global__ void fill_kernel(const int* __restrict__ ei32) {
    int e = blockIdx.x * blockDim.x + threadIdx.x;
    if (e < N_EDGES) {
        int d = load_idx(ei32, (long long)N_EDGES + e);
        int s = load_idx(ei32, e);
        int p = atomicAdd(&g_cursor[d], 1);
        if (p >= 0 && p < N_EDGES) g_src[p] = s;
    }
}

// ---------------- mean aggregation: one warp per dst node ----------------
__global__ void agg_kernel(const float* __restrict__ xext, int sel, int nrows) {
    int gw = (int)((blockIdx.x * blockDim.x + threadIdx.x) >> 5);
    int lane = threadIdx.x & 31;
    if (gw >= nrows) return;
    const float* feat = (sel == 0) ? xext : ((sel == 1) ? g_featA : g_featB);
    const float4* base = (const float4*)feat;
    int s = g_start[gw];
    int n = g_deg[gw];
    float4 acc = make_float4(0.f, 0.f, 0.f, 0.f);
    #pragma unroll 4
    for (int e = 0; e < n; e++) {
        int src = g_src[s + e];
        float4 v = base[src * 32 + lane];          // x fits in L2 -> L2-rate gather
        acc.x += v.x; acc.y += v.y; acc.z += v.z; acc.w += v.w;
    }
    float inv = (n > 0) ? 1.0f / (float)n : 0.0f;
    ((float4*)g_agg)[gw * 32 + lane] =
        make_float4(acc.x * inv, acc.y * inv, acc.z * inv, acc.w * inv);
}

// ---------------- fused GEMM + bias + PReLU ----------------
// out = PReLU( g_agg @ Wl^T + bl + X @ Wr^T ), per-channel slope pa.
// Tile: BM=128, BN=128, BK=16, 256 threads, 8x8 register tile, 2 CTAs/SM.
__global__ __launch_bounds__(256, 2) void gemm_kernel(
    const float* __restrict__ xext, int xsel,
    const float* __restrict__ Wl, const float* __restrict__ bl,
    const float* __restrict__ Wr, const float* __restrict__ pa,
    float* __restrict__ oext, int osel, int M)
{
    const float* X = (xsel == 0) ? xext : ((xsel == 1) ? g_featA : g_featB);
    float*       O = (osel == 0) ? oext : ((osel == 1) ? g_featA : g_featB);

    __shared__ float As[16][132];   // [k][m], +4 pad keeps 16B align, breaks conflicts
    __shared__ float Bs[16][132];   // [k][n]

    int tid = threadIdx.x;
    int block_row = blockIdx.x * 128;
    int tx = tid & 15;              // col group: cols tx*8 .. +7
    int ty = tid >> 4;              // row group: rows ty*8 .. +7

    float acc[8][8];
    #pragma unroll
    for (int i = 0; i < 8; i++)
        #pragma unroll
        for (int j = 0; j < 8; j++) acc[i][j] = 0.f;

    #pragma unroll 1
    for (int chunk = 0; chunk < 16; chunk++) {
        const float* Aptr; const float* Wptr; int kbase;
        if (chunk < 8) { Aptr = g_agg; Wptr = Wl; kbase = chunk * 16; }
        else           { Aptr = X;     Wptr = Wr; kbase = (chunk - 8) * 16; }

        // A tile: 128 rows x 16 k (transposed into As), 2 float4 per thread
        #pragma unroll
        for (int l = 0; l < 2; l++) {
            int s  = tid + l * 256;
            int r  = s >> 2;                 // 0..127
            int kq = s & 3;                  // 0..3
            int grow = block_row + r;
            float4 v = make_float4(0.f, 0.f, 0.f, 0.f);
            if (grow < M)
                v = *(const float4*)(Aptr + (size_t)grow * CH + kbase + kq * 4);
            As[kq * 4 + 0][r] = v.x;
            As[kq * 4 + 1][r] = v.y;
            As[kq * 4 + 2][r] = v.z;
            As[kq * 4 + 3][r] = v.w;
        }
        // W tile: Bs[k][n] = W[n][kbase+k], 2 float4 per thread (always full)
        #pragma unroll
        for (int l = 0; l < 2; l++) {
            int s  = tid + l * 256;
            int n  = s >> 2;
            int kq = s & 3;
            float4 v = *(const float4*)(Wptr + n * CH + kbase + kq * 4);
            Bs[kq * 4 + 0][n] = v.x;
            Bs[kq * 4 + 1][n] = v.y;
            Bs[kq * 4 + 2][n] = v.z;
            Bs[kq * 4 + 3][n] = v.w;
        }
        __syncthreads();

        #pragma unroll
        for (int k = 0; k < 16; k++) {
            float4 a0 = *(const float4*)&As[k][ty * 8];
            float4 a1 = *(const float4*)&As[k][ty * 8 + 4];
            float4 b0 = *(const float4*)&Bs[k][tx * 8];
            float4 b1 = *(const float4*)&Bs[k][tx * 8 + 4];
            float a[8] = {a0.x, a0.y, a0.z, a0.w, a1.x, a1.y, a1.z, a1.w};
            float b[8] = {b0.x, b0.y, b0.z, b0.w, b1.x, b1.y, b1.z, b1.w};
            #pragma unroll
            for (int i = 0; i < 8; i++)
                #pragma unroll
                for (int j = 0; j < 8; j++)
                    acc[i][j] += a[i] * b[j];
        }
        __syncthreads();
    }

    // epilogue: bias + PReLU, 2x float4 stores per row
    int col = tx * 8;
    float4 bb0 = *(const float4*)(bl + col);
    float4 bb1 = *(const float4*)(bl + col + 4);
    float4 aa0 = *(const float4*)(pa + col);
    float4 aa1 = *(const float4*)(pa + col + 4);
    float bb[8] = {bb0.x, bb0.y, bb0.z, bb0.w, bb1.x, bb1.y, bb1.z, bb1.w};
    float aa[8] = {aa0.x, aa0.y, aa0.z, aa0.w, aa1.x, aa1.y, aa1.z, aa1.w};
    #pragma unroll
    for (int i = 0; i < 8; i++) {
        int grow = block_row + ty * 8 + i;
        if (grow < M) {
            float o[8];
            #pragma unroll
            for (int j = 0; j < 8; j++) {
                float v = acc[i][j] + bb[j];
                o[j] = (v > 0.f) ? v : aa[j] * v;
            }
            *(float4*)(O + (size_t)grow * CH + col)     = make_float4(o[0], o[1], o[2], o[3]);
            *(float4*)(O + (size_t)grow * CH + col + 4) = make_float4(o[4], o[5], o[6], o[7]);
        }
    }
}

// ---------------- launch ----------------
extern "C" void kernel_launch(void* const* d_in, const int* in_sizes, int n_in,
                              void* d_out, int out_size) {
    const float* x    = (const float*)d_in[0];
    const int*   ei32 = (const int*)d_in[1];
    int wb = n_in - 12;                          // weights are the LAST 12 inputs
    const float* Wl0 = (const float*)d_in[wb + 0];
    const float* bl0 = (const float*)d_in[wb + 1];
    const float* Wr0 = (const float*)d_in[wb + 2];
    const float* a0  = (const float*)d_in[wb + 3];
    const float* Wl1 = (const float*)d_in[wb + 4];
    const float* bl1 = (const float*)d_in[wb + 5];
    const float* Wr1 = (const float*)d_in[wb + 6];
    const float* a1  = (const float*)d_in[wb + 7];
    const float* Wl2 = (const float*)d_in[wb + 8];
    const float* bl2 = (const float*)d_in[wb + 9];
    const float* Wr2 = (const float*)d_in[wb + 10];
    const float* a2  = (const float*)d_in[wb + 11];
    float* out = (float*)d_out;

    const int EB = (N_EDGES + 255) / 256;        // 3125
    const int NB = (N_NODES + 255) / 256;        // 196
    const int GM = (N_NODES + 127) / 128;        // 391

    // CSR build
    init_kernel<<<NB + 1, 256>>>(ei32);
    hist_kernel<<<EB, 256>>>(ei32);
    scan_local_kernel<<<SCAN_BLOCKS, SCAN_CHUNK>>>();
    scan_part_kernel<<<1, 128>>>();
    scan_add_kernel<<<SCAN_BLOCKS, SCAN_CHUNK>>>();
    fill_kernel<<<EB, 256>>>(ei32);

    // Layer 1
    agg_kernel<<<(N_NODES + 7) / 8, 256>>>(x, 0, N_NODES);
    gemm_kernel<<<GM, 256>>>(x, 0, Wl0, bl0, Wr0, a0, nullptr, 1, N_NODES);

    // Layer 2
    agg_kernel<<<(N_NODES + 7) / 8, 256>>>(nullptr, 1, N_NODES);
    gemm_kernel<<<GM, 256>>>(nullptr, 1, Wl1, bl1, Wr1, a1, nullptr, 2, N_NODES);

    // Layer 3: only rows < 1024 needed
    agg_kernel<<<1024 / 8, 256>>>(nullptr, 2, 1024);
    gemm_kernel<<<1024 / 128, 256>>>(nullptr, 2, Wl2, bl2, Wr2, a2, out, 0, 1024);
}

// round 9
// speedup vs baseline: 1.1270x; 1.1270x over previous
#include <cuda_runtime.h>

#define N_NODES 50000
#define N_EDGES 800000
#define CH 128
#define SCAN_CHUNK 512
#define SCAN_BLOCKS ((N_NODES + SCAN_CHUNK - 1) / SCAN_CHUNK)   // 98

// ---------------- scratch (static device globals; no runtime alloc) ----------------
__device__ float g_featA[N_NODES * CH];
__device__ float g_featB[N_NODES * CH];
__device__ float g_agg[N_NODES * CH];
__device__ int   g_deg[N_NODES];
__device__ int   g_start[N_NODES];
__device__ int   g_cursor[N_NODES];
__device__ int   g_src[N_EDGES];
__device__ int   g_part[SCAN_BLOCKS];
__device__ int   g_is64;

// ---------------- init: block 0 detects edge-index layout, others zero g_deg --------
// int64 layout: hi int32 word of the first 4096 edges is always 0 (ids < 50000).
__global__ void init_kernel(const int* __restrict__ ei32) {
    if (blockIdx.x == 0) {
        __shared__ int any_nz;
        if (threadIdx.x == 0) any_nz = 0;
        __syncthreads();
        for (int i = threadIdx.x; i < 4096; i += blockDim.x)
            if (ei32[2 * i + 1] != 0) any_nz = 1;    // benign race
        __syncthreads();
        if (threadIdx.x == 0) g_is64 = any_nz ? 0 : 1;
    } else {
        int i = (blockIdx.x - 1) * blockDim.x + threadIdx.x;
        if (i < N_NODES) g_deg[i] = 0;
    }
}

__device__ __forceinline__ int load_idx(const int* ei32, long long pos) {
    int v = g_is64 ? ei32[2 * pos] : ei32[pos];
    if (v < 0 || v >= N_NODES) v = 0;                // crash-proof clamp
    return v;
}

__global__ void hist_kernel(const int* __restrict__ ei32) {
    int e = blockIdx.x * blockDim.x + threadIdx.x;
    if (e < N_EDGES) atomicAdd(&g_deg[load_idx(ei32, (long long)N_EDGES + e)], 1);
}

// ---------------- parallel 3-phase exclusive scan of g_deg -> g_start/g_cursor ------
__global__ void scan_local_kernel() {   // 98 blocks x 512: local excl scan + block sum
    __shared__ int warp_sums[16];
    int tid = threadIdx.x, lane = tid & 31, wid = tid >> 5;
    int i = blockIdx.x * SCAN_CHUNK + tid;
    int v = (i < N_NODES) ? g_deg[i] : 0;
    int val = v;
    #pragma unroll
    for (int off = 1; off < 32; off <<= 1) {
        int t = __shfl_up_sync(0xffffffffu, val, off);
        if (lane >= off) val += t;
    }
    if (lane == 31) warp_sums[wid] = val;
    __syncthreads();
    if (wid == 0 && lane < 16) {
        int s = warp_sums[lane], sv = s;
        #pragma unroll
        for (int off = 1; off < 16; off <<= 1) {
            int t = __shfl_up_sync(0x0000ffffu, sv, off);
            if (lane >= off) sv += t;
        }
        warp_sums[lane] = sv - s;       // exclusive warp offsets
    }
    __syncthreads();
    int excl = val - v + warp_sums[wid];
    if (i < N_NODES) g_start[i] = excl;
    if (tid == SCAN_CHUNK - 1) g_part[blockIdx.x] = excl + v;
}

__global__ void scan_part_kernel() {    // 1 block x 128: excl scan of 98 partials
    __shared__ int sh[128];
    int tid = threadIdx.x;
    int v = (tid < SCAN_BLOCKS) ? g_part[tid] : 0;
    sh[tid] = v;
    __syncthreads();
    for (int off = 1; off < 128; off <<= 1) {
        int t = (tid >= off) ? sh[tid - off] : 0;
        __syncthreads();
        sh[tid] += t;
        __syncthreads();
    }
    if (tid < SCAN_BLOCKS) g_part[tid] = sh[tid] - v;
}

__global__ void scan_add_kernel() {     // 98 blocks x 512: add block offset
    int i = blockIdx.x * SCAN_CHUNK + threadIdx.x;
    if (i < N_NODES) {
        int val = g_start[i] + g_part[blockIdx.x];
        g_start[i]  = val;
        g_cursor[i] = val;
    }
}

__global__ void fill_kernel(const int* __restrict__ ei32) {
    int e = blockIdx.x * blockDim.x + threadIdx.x;
    if (e < N_EDGES) {
        int d = load_idx(ei32, (long long)N_EDGES + e);
        int s = load_idx(ei32, e);
        int p = atomicAdd(&g_cursor[d], 1);
        if (p >= 0 && p < N_EDGES) g_src[p] = s;
    }
}

// ---------------- mean aggregation: one warp per dst node ----------------
__global__ void agg_kernel(const float* __restrict__ xext, int sel, int nrows) {
    int gw = (int)((blockIdx.x * blockDim.x + threadIdx.x) >> 5);
    int lane = threadIdx.x & 31;
    if (gw >= nrows) return;
    const float* feat = (sel == 0) ? xext : ((sel == 1) ? g_featA : g_featB);
    const float4* base = (const float4*)feat;
    int s = g_start[gw];
    int n = g_deg[gw];
    float4 acc = make_float4(0.f, 0.f, 0.f, 0.f);
    for (int e = 0; e < n; e++) {
        int src = g_src[s + e];
        float4 v = base[src * 32 + lane];          // x fits in L2 -> L2-rate gather
        acc.x += v.x; acc.y += v.y; acc.z += v.z; acc.w += v.w;
    }
    float inv = (n > 0) ? 1.0f / (float)n : 0.0f;
    ((float4*)g_agg)[gw * 32 + lane] =
        make_float4(acc.x * inv, acc.y * inv, acc.z * inv, acc.w * inv);
}

// ---------------- fused GEMM + bias + PReLU (R4 config: 64x128, 8x4, 4 CTA/SM) -----
// out = PReLU( g_agg @ Wl^T + bl + X @ Wr^T ), per-channel slope pa.
__global__ __launch_bounds__(256, 4) void gemm_kernel(
    const float* __restrict__ xext, int xsel,
    const float* __restrict__ Wl, const float* __restrict__ bl,
    const float* __restrict__ Wr, const float* __restrict__ pa,
    float* __restrict__ oext, int osel, int M)
{
    const float* X = (xsel == 0) ? xext : ((xsel == 1) ? g_featA : g_featB);
    float*       O = (osel == 0) ? oext : ((osel == 1) ? g_featA : g_featB);

    __shared__ float As[16][65];    // [k][m], padded: broadcast reads
    __shared__ float Bs[16][132];   // [k][n], padded +4 keeps 16B alignment

    int tid = threadIdx.x;
    int block_row = blockIdx.x * 64;
    int tn = tid & 31;    // column group: cols tn*4 .. tn*4+3
    int tm = tid >> 5;    // warp id = row group: rows tm*8 .. tm*8+7

    float acc[8][4];
    #pragma unroll
    for (int i = 0; i < 8; i++)
        #pragma unroll
        for (int j = 0; j < 4; j++) acc[i][j] = 0.f;

    #pragma unroll 1
    for (int chunk = 0; chunk < 16; chunk++) {
        const float* Aptr; const float* Wptr; int kbase;
        if (chunk < 8) { Aptr = g_agg; Wptr = Wl; kbase = chunk * 16; }
        else           { Aptr = X;     Wptr = Wr; kbase = (chunk - 8) * 16; }

        // A tile: rows block_row..+63, k kbase..+15 (transposed into As)
        {
            int r  = tid >> 2;            // 0..63
            int kq = tid & 3;             // 0..3
            int grow = block_row + r;
            float4 v = make_float4(0.f, 0.f, 0.f, 0.f);
            if (grow < M)
                v = *(const float4*)(Aptr + (size_t)grow * CH + kbase + kq * 4);
            As[kq * 4 + 0][r] = v.x;
            As[kq * 4 + 1][r] = v.y;
            As[kq * 4 + 2][r] = v.z;
            As[kq * 4 + 3][r] = v.w;
        }
        // W tile: Bs[k][n] = W[n][kbase+k]
        {
            #pragma unroll
            for (int l = 0; l < 2; l++) {
                int s  = tid + l * 256;   // 0..511
                int n  = s >> 2;          // 0..127
                int kq = s & 3;
                float4 v = *(const float4*)(Wptr + n * CH + kbase + kq * 4);
                Bs[kq * 4 + 0][n] = v.x;
                Bs[kq * 4 + 1][n] = v.y;
                Bs[kq * 4 + 2][n] = v.z;
                Bs[kq * 4 + 3][n] = v.w;
            }
        }
        __syncthreads();

        #pragma unroll
        for (int k = 0; k < 16; k++) {
            float4 b4 = *(const float4*)&Bs[k][tn * 4];  // conflict-free LDS.128
            float a[8];
            #pragma unroll
            for (int i = 0; i < 8; i++) a[i] = As[k][tm * 8 + i];  // warp broadcast
            #pragma unroll
            for (int i = 0; i < 8; i++) {
                acc[i][0] += a[i] * b4.x;
                acc[i][1] += a[i] * b4.y;
                acc[i][2] += a[i] * b4.z;
                acc[i][3] += a[i] * b4.w;
            }
        }
        __syncthreads();
    }

    // epilogue: bias + PReLU, float4 stores
    int col = tn * 4;
    float4 bb = *(const float4*)(bl + col);
    float4 aa = *(const float4*)(pa + col);
    #pragma unroll
    for (int i = 0; i < 8; i++) {
        int grow = block_row + tm * 8 + i;
        if (grow < M) {
            float v0 = acc[i][0] + bb.x;
            float v1 = acc[i][1] + bb.y;
            float v2 = acc[i][2] + bb.z;
            float v3 = acc[i][3] + bb.w;
            float4 o;
            o.x = (v0 > 0.f) ? v0 : aa.x * v0;
            o.y = (v1 > 0.f) ? v1 : aa.y * v1;
            o.z = (v2 > 0.f) ? v2 : aa.z * v2;
            o.w = (v3 > 0.f) ? v3 : aa.w * v3;
            *(float4*)(O + (size_t)grow * CH + col) = o;
        }
    }
}

// ---------------- launch ----------------
extern "C" void kernel_launch(void* const* d_in, const int* in_sizes, int n_in,
                              void* d_out, int out_size) {
    const float* x    = (const float*)d_in[0];
    const int*   ei32 = (const int*)d_in[1];
    int wb = n_in - 12;                          // weights are the LAST 12 inputs
    const float* Wl0 = (const float*)d_in[wb + 0];
    const float* bl0 = (const float*)d_in[wb + 1];
    const float* Wr0 = (const float*)d_in[wb + 2];
    const float* a0  = (const float*)d_in[wb + 3];
    const float* Wl1 = (const float*)d_in[wb + 4];
    const float* bl1 = (const float*)d_in[wb + 5];
    const float* Wr1 = (const float*)d_in[wb + 6];
    const float* a1  = (const float*)d_in[wb + 7];
    const float* Wl2 = (const float*)d_in[wb + 8];
    const float* bl2 = (const float*)d_in[wb + 9];
    const float* Wr2 = (const float*)d_in[wb + 10];
    const float* a2  = (const float*)d_in[wb + 11];
    float* out = (float*)d_out;

    const int EB = (N_EDGES + 255) / 256;        // 3125
    const int NB = (N_NODES + 255) / 256;        // 196
    const int GM = (N_NODES + 63) / 64;          // 782

    // CSR build
    init_kernel<<<NB + 1, 256>>>(ei32);
    hist_kernel<<<EB, 256>>>(ei32);
    scan_local_kernel<<<SCAN_BLOCKS, SCAN_CHUNK>>>();
    scan_part_kernel<<<1, 128>>>();
    scan_add_kernel<<<SCAN_BLOCKS, SCAN_CHUNK>>>();
    fill_kernel<<<EB, 256>>>(ei32);

    // Layer 1
    agg_kernel<<<(N_NODES + 7) / 8, 256>>>(x, 0, N_NODES);
    gemm_kernel<<<GM, 256>>>(x, 0, Wl0, bl0, Wr0, a0, nullptr, 1, N_NODES);

    // Layer 2
    agg_kernel<<<(N_NODES + 7) / 8, 256>>>(nullptr, 1, N_NODES);
    gemm_kernel<<<GM, 256>>>(nullptr, 1, Wl1, bl1, Wr1, a1, nullptr, 2, N_NODES);

    // Layer 3: only rows < 1024 needed
    agg_kernel<<<1024 / 8, 256>>>(nullptr, 2, 1024);
    gemm_kernel<<<1024 / 64, 256>>>(nullptr, 2, Wl2, bl2, Wr2, a2, out, 0, 1024);
}

// round 12
// speedup vs baseline: 1.5904x; 1.4112x over previous
#include <cuda_runtime.h>
#include <cuda_bf16.h>
#include <mma.h>
#include <cstdint>

using namespace nvcuda;

#define N_NODES 50000
#define N_EDGES 800000
#define CH 128
#define SCAN_CHUNK 512
#define SCAN_BLOCKS ((N_NODES + SCAN_CHUNK - 1) / SCAN_CHUNK)   // 98

// ---------------- scratch (static device globals; no runtime alloc) ----------------
__device__ float g_featA[N_NODES * CH];
__device__ float g_featB[N_NODES * CH];
__device__ float g_agg[N_NODES * CH];
__device__ int   g_deg[N_NODES];
__device__ int   g_start[N_NODES];
__device__ int   g_cursor[N_NODES];
__device__ int   g_src[N_EDGES];
__device__ int   g_part[SCAN_BLOCKS];
__device__ int   g_is64;

// ---------------- init: block 0 detects edge-index layout, others zero g_deg --------
__global__ void init_kernel(const int* __restrict__ ei32) {
    if (blockIdx.x == 0) {
        __shared__ int any_nz;
        if (threadIdx.x == 0) any_nz = 0;
        __syncthreads();
        for (int i = threadIdx.x; i < 4096; i += blockDim.x)
            if (ei32[2 * i + 1] != 0) any_nz = 1;    // benign race
        __syncthreads();
        if (threadIdx.x == 0) g_is64 = any_nz ? 0 : 1;
    } else {
        int i = (blockIdx.x - 1) * blockDim.x + threadIdx.x;
        if (i < N_NODES) g_deg[i] = 0;
    }
}

__device__ __forceinline__ int load_idx(const int* ei32, long long pos) {
    int v = g_is64 ? ei32[2 * pos] : ei32[pos];
    if (v < 0 || v >= N_NODES) v = 0;
    return v;
}

__global__ void hist_kernel(const int* __restrict__ ei32) {
    int e = blockIdx.x * blockDim.x + threadIdx.x;
    if (e < N_EDGES) atomicAdd(&g_deg[load_idx(ei32, (long long)N_EDGES + e)], 1);
}

// ---------------- parallel 3-phase exclusive scan ----------------
__global__ void scan_local_kernel() {
    __shared__ int warp_sums[16];
    int tid = threadIdx.x, lane = tid & 31, wid = tid >> 5;
    int i = blockIdx.x * SCAN_CHUNK + tid;
    int v = (i < N_NODES) ? g_deg[i] : 0;
    int val = v;
    #pragma unroll
    for (int off = 1; off < 32; off <<= 1) {
        int t = __shfl_up_sync(0xffffffffu, val, off);
        if (lane >= off) val += t;
    }
    if (lane == 31) warp_sums[wid] = val;
    __syncthreads();
    if (wid == 0 && lane < 16) {
        int s = warp_sums[lane], sv = s;
        #pragma unroll
        for (int off = 1; off < 16; off <<= 1) {
            int t = __shfl_up_sync(0x0000ffffu, sv, off);
            if (lane >= off) sv += t;
        }
        warp_sums[lane] = sv - s;
    }
    __syncthreads();
    int excl = val - v + warp_sums[wid];
    if (i < N_NODES) g_start[i] = excl;
    if (tid == SCAN_CHUNK - 1) g_part[blockIdx.x] = excl + v;
}

__global__ void scan_part_kernel() {
    __shared__ int sh[128];
    int tid = threadIdx.x;
    int v = (tid < SCAN_BLOCKS) ? g_part[tid] : 0;
    sh[tid] = v;
    __syncthreads();
    for (int off = 1; off < 128; off <<= 1) {
        int t = (tid >= off) ? sh[tid - off] : 0;
        __syncthreads();
        sh[tid] += t;
        __syncthreads();
    }
    if (tid < SCAN_BLOCKS) g_part[tid] = sh[tid] - v;
}

__global__ void scan_add_kernel() {
    int i = blockIdx.x * SCAN_CHUNK + threadIdx.x;
    if (i < N_NODES) {
        int val = g_start[i] + g_part[blockIdx.x];
        g_start[i]  = val;
        g_cursor[i] = val;
    }
}

__global__ void fill_kernel(const int* __restrict__ ei32) {
    int e = blockIdx.x * blockDim.x + threadIdx.x;
    if (e < N_EDGES) {
        int d = load_idx(ei32, (long long)N_EDGES + e);
        int s = load_idx(ei32, e);
        int p = atomicAdd(&g_cursor[d], 1);
        if (p >= 0 && p < N_EDGES) g_src[p] = s;
    }
}

// ---------------- mean aggregation: one warp per dst node ----------------
__global__ void agg_kernel(const float* __restrict__ xext, int sel, int nrows) {
    int gw = (int)((blockIdx.x * blockDim.x + threadIdx.x) >> 5);
    int lane = threadIdx.x & 31;
    if (gw >= nrows) return;
    const float* feat = (sel == 0) ? xext : ((sel == 1) ? g_featA : g_featB);
    const float4* base = (const float4*)feat;
    int s = g_start[gw];
    int n = g_deg[gw];
    float4 acc = make_float4(0.f, 0.f, 0.f, 0.f);
    for (int e = 0; e < n; e++) {
        int src = g_src[s + e];
        float4 v = base[src * 32 + lane];
        acc.x += v.x; acc.y += v.y; acc.z += v.z; acc.w += v.w;
    }
    float inv = (n > 0) ? 1.0f / (float)n : 0.0f;
    ((float4*)g_agg)[gw * 32 + lane] =
        make_float4(acc.x * inv, acc.y * inv, acc.z * inv, acc.w * inv);
}

// ================= WMMA bf16-split GEMM + bias + PReLU =================
// out = PReLU( g_agg @ Wl^T + bl + X @ Wr^T ).
// fp32 operand split x = hi + lo (bf16); acc += hi*hi + hi*lo + lo*hi (fp32 TC accum).
// CTA: 128 M x 128 N; 8 warps (4x2), warp tile 32x64, frags 2x4 of 16x16.
// Two accumulate passes over the SAME register accumulators: (agg,Wl) then (X,Wr).

#define GW_LD   136                      // bf16 elements per tile row (272B: ldmatrix conflict-free)
#define GW_TILE (128 * GW_LD * 2)        // 34816 B
#define GW_AHI  0
#define GW_ALO  (GW_TILE)
#define GW_BHI  (2 * GW_TILE)
#define GW_BLO  (3 * GW_TILE)
#define GW_SMEM (4 * GW_TILE)            // 139264 B
#define GW_SLD  132                      // fp32 stage row stride

__device__ __forceinline__ void split_store(__nv_bfloat16* hi, __nv_bfloat16* lo,
                                            int eoff, float4 v) {
    __nv_bfloat16 h0 = __float2bfloat16(v.x);
    __nv_bfloat16 h1 = __float2bfloat16(v.y);
    __nv_bfloat16 h2 = __float2bfloat16(v.z);
    __nv_bfloat16 h3 = __float2bfloat16(v.w);
    __nv_bfloat16 l0 = __float2bfloat16(v.x - __bfloat162float(h0));
    __nv_bfloat16 l1 = __float2bfloat16(v.y - __bfloat162float(h1));
    __nv_bfloat16 l2 = __float2bfloat16(v.z - __bfloat162float(h2));
    __nv_bfloat16 l3 = __float2bfloat16(v.w - __bfloat162float(h3));
    uint2 hv = make_uint2(((uint32_t)__bfloat16_as_ushort(h1) << 16) | __bfloat16_as_ushort(h0),
                          ((uint32_t)__bfloat16_as_ushort(h3) << 16) | __bfloat16_as_ushort(h2));
    uint2 lv = make_uint2(((uint32_t)__bfloat16_as_ushort(l1) << 16) | __bfloat16_as_ushort(l0),
                          ((uint32_t)__bfloat16_as_ushort(l3) << 16) | __bfloat16_as_ushort(l2));
    *(uint2*)(hi + eoff) = hv;
    *(uint2*)(lo + eoff) = lv;
}

__global__ __launch_bounds__(256, 1) void gemm_wmma_kernel(
    const float* __restrict__ xext, int xsel,
    const float* __restrict__ Wl, const float* __restrict__ bl,
    const float* __restrict__ Wr, const float* __restrict__ pa,
    float* __restrict__ oext, int osel, int M)
{
    extern __shared__ char dsm[];
    const float* X = (xsel == 0) ? xext : ((xsel == 1) ? g_featA : g_featB);
    float*       O = (osel == 0) ? oext : ((osel == 1) ? g_featA : g_featB);

    __nv_bfloat16* Ahi = (__nv_bfloat16*)(dsm + GW_AHI);
    __nv_bfloat16* Alo = (__nv_bfloat16*)(dsm + GW_ALO);
    __nv_bfloat16* Bhi = (__nv_bfloat16*)(dsm + GW_BHI);
    __nv_bfloat16* Blo = (__nv_bfloat16*)(dsm + GW_BLO);

    int tid = threadIdx.x;
    int wid = tid >> 5;
    int warp_m = wid >> 1;    // 0..3 -> rows warp_m*32
    int warp_n = wid & 1;     // 0..1 -> cols warp_n*64
    int block_row = blockIdx.x * 128;

    wmma::fragment<wmma::accumulator, 16, 16, 16, float> acc[2][4];
    #pragma unroll
    for (int i = 0; i < 2; i++)
        #pragma unroll
        for (int j = 0; j < 4; j++) wmma::fill_fragment(acc[i][j], 0.f);

    #pragma unroll 1
    for (int p = 0; p < 2; p++) {
        const float* Ap = p ? X  : g_agg;
        const float* Wp = p ? Wr : Wl;
        // fill: 4096 float4-groups each for A and W; 16 per thread
        #pragma unroll 4
        for (int it = 0; it < 16; it++) {
            int g  = tid + it * 256;
            int r  = g >> 5;              // 0..127
            int k0 = (g & 31) << 2;       // 0..124
            int eoff = r * GW_LD + k0;
            float4 av = make_float4(0.f, 0.f, 0.f, 0.f);
            if (block_row + r < M)
                av = *(const float4*)(Ap + (size_t)(block_row + r) * CH + k0);
            split_store(Ahi, Alo, eoff, av);
            float4 wv = *(const float4*)(Wp + (size_t)r * CH + k0);
            split_store(Bhi, Blo, eoff, wv);
        }
        __syncthreads();

        #pragma unroll 1
        for (int k0 = 0; k0 < 128; k0 += 16) {
            wmma::fragment<wmma::matrix_a, 16, 16, 16, __nv_bfloat16, wmma::row_major> a_hi[2], a_lo[2];
            wmma::fragment<wmma::matrix_b, 16, 16, 16, __nv_bfloat16, wmma::col_major> b_hi[4], b_lo[4];
            #pragma unroll
            for (int i = 0; i < 2; i++) {
                int r0 = warp_m * 32 + i * 16;
                wmma::load_matrix_sync(a_hi[i], Ahi + r0 * GW_LD + k0, GW_LD);
                wmma::load_matrix_sync(a_lo[i], Alo + r0 * GW_LD + k0, GW_LD);
            }
            #pragma unroll
            for (int j = 0; j < 4; j++) {
                int n0 = warp_n * 64 + j * 16;
                wmma::load_matrix_sync(b_hi[j], Bhi + n0 * GW_LD + k0, GW_LD);
                wmma::load_matrix_sync(b_lo[j], Blo + n0 * GW_LD + k0, GW_LD);
            }
            #pragma unroll
            for (int i = 0; i < 2; i++)
                #pragma unroll
                for (int j = 0; j < 4; j++) {
                    wmma::mma_sync(acc[i][j], a_hi[i], b_hi[j], acc[i][j]);
                    wmma::mma_sync(acc[i][j], a_hi[i], b_lo[j], acc[i][j]);
                    wmma::mma_sync(acc[i][j], a_lo[i], b_hi[j], acc[i][j]);
                }
        }
        __syncthreads();   // all reads done before next pass overwrites tiles
    }

    // stage accumulators to SMEM (reuse tile memory), then fused bias+PReLU writeout
    float* stage = (float*)dsm;
    #pragma unroll
    for (int i = 0; i < 2; i++)
        #pragma unroll
        for (int j = 0; j < 4; j++) {
            int r0 = warp_m * 32 + i * 16;
            int n0 = warp_n * 64 + j * 16;
            wmma::store_matrix_sync(stage + r0 * GW_SLD + n0, acc[i][j], GW_SLD,
                                    wmma::mem_row_major);
        }
    __syncthreads();

    #pragma unroll 4
    for (int it = 0; it < 16; it++) {
        int g  = tid + it * 256;
        int r  = g >> 5;
        int c0 = (g & 31) << 2;
        int grow = block_row + r;
        if (grow < M) {
            float4 v  = *(const float4*)(stage + r * GW_SLD + c0);
            float4 bb = *(const float4*)(bl + c0);
            float4 aa = *(const float4*)(pa + c0);
            float v0 = v.x + bb.x, v1 = v.y + bb.y, v2 = v.z + bb.z, v3 = v.w + bb.w;
            float4 o;
            o.x = (v0 > 0.f) ? v0 : aa.x * v0;
            o.y = (v1 > 0.f) ? v1 : aa.y * v1;
            o.z = (v2 > 0.f) ? v2 : aa.z * v2;
            o.w = (v3 > 0.f) ? v3 : aa.w * v3;
            *(float4*)(O + (size_t)grow * CH + c0) = o;
        }
    }
}

// ---------------- launch ----------------
extern "C" void kernel_launch(void* const* d_in, const int* in_sizes, int n_in,
                              void* d_out, int out_size) {
    const float* x    = (const float*)d_in[0];
    const int*   ei32 = (const int*)d_in[1];
    int wb = n_in - 12;                          // weights are the LAST 12 inputs
    const float* Wl0 = (const float*)d_in[wb + 0];
    const float* bl0 = (const float*)d_in[wb + 1];
    const float* Wr0 = (const float*)d_in[wb + 2];
    const float* a0  = (const float*)d_in[wb + 3];
    const float* Wl1 = (const float*)d_in[wb + 4];
    const float* bl1 = (const float*)d_in[wb + 5];
    const float* Wr1 = (const float*)d_in[wb + 6];
    const float* a1  = (const float*)d_in[wb + 7];
    const float* Wl2 = (const float*)d_in[wb + 8];
    const float* bl2 = (const float*)d_in[wb + 9];
    const float* Wr2 = (const float*)d_in[wb + 10];
    const float* a2  = (const float*)d_in[wb + 11];
    float* out = (float*)d_out;

    const int EB = (N_EDGES + 255) / 256;        // 3125
    const int NB = (N_NODES + 255) / 256;        // 196
    const int GM = (N_NODES + 127) / 128;        // 391

    cudaFuncSetAttribute(gemm_wmma_kernel,
                         cudaFuncAttributeMaxDynamicSharedMemorySize, GW_SMEM);

    // CSR build
    init_kernel<<<NB + 1, 256>>>(ei32);
    hist_kernel<<<EB, 256>>>(ei32);
    scan_local_kernel<<<SCAN_BLOCKS, SCAN_CHUNK>>>();
    scan_part_kernel<<<1, 128>>>();
    scan_add_kernel<<<SCAN_BLOCKS, SCAN_CHUNK>>>();
    fill_kernel<<<EB, 256>>>(ei32);

    // Layer 1
    agg_kernel<<<(N_NODES + 7) / 8, 256>>>(x, 0, N_NODES);
    gemm_wmma_kernel<<<GM, 256, GW_SMEM>>>(x, 0, Wl0, bl0, Wr0, a0, nullptr, 1, N_NODES);

    // Layer 2
    agg_kernel<<<(N_NODES + 7) / 8, 256>>>(nullptr, 1, N_NODES);
    gemm_wmma_kernel<<<GM, 256, GW_SMEM>>>(nullptr, 1, Wl1, bl1, Wr1, a1, nullptr, 2, N_NODES);

    // Layer 3: only rows < 1024 needed
    agg_kernel<<<1024 / 8, 256>>>(nullptr, 2, 1024);
    gemm_wmma_kernel<<<1024 / 128, 256, GW_SMEM>>>(nullptr, 2, Wl2, bl2, Wr2, a2, out, 0, 1024);
}